// round 7
// baseline (speedup 1.0000x reference)
#include <cuda_runtime.h>
#include <cuda_bf16.h>
#include <stdint.h>

// Problem constants
#define Bv 2
#define Nv 4
#define Dv 48
#define Hv 28
#define Wv 60
#define Cv 64
#define NXv 192
#define NYv 192
#define NZv 1
#define NYNX (NYv * NXv)

// Channel-contiguous staging accumulator: [B*NY*NX][64] floats (18.9 MB).
// BSS-zeroed at module load; the transpose kernel restores it to zero at its
// tail every launch, so it is always zero when the next scatter begins.
__device__ float4 g_staging4[(size_t)Bv * NYv * NXv * (Cv / 4)];

// ---------------------------------------------------------------------------
// Per-block setup (in smem): invert intrinsics element-wise by det (matches
// LU back-substitution bit-for-bit on this matrix structure — validated
// rel_err 2.5e-7 across R1-R5), combine = R @ inv(K), stash translation.
// ---------------------------------------------------------------------------
__device__ __forceinline__ void compute_combine(
    const float* __restrict__ intr, const float* __restrict__ pose,
    int i, float* cm, float* tr) {
    const float* K = intr + i * 9;
    float a00 = K[0], a01 = K[1], a02 = K[2];
    float a10 = K[3], a11 = K[4], a12 = K[5];
    float a20 = K[6], a21 = K[7], a22 = K[8];

    float det = __fadd_rn(
        __fsub_rn(__fmul_rn(a00, __fsub_rn(__fmul_rn(a11, a22), __fmul_rn(a12, a21))),
                  __fmul_rn(a01, __fsub_rn(__fmul_rn(a10, a22), __fmul_rn(a12, a20)))),
        __fmul_rn(a02, __fsub_rn(__fmul_rn(a10, a21), __fmul_rn(a11, a20))));

    float inv[9];
    inv[0] = __fdiv_rn(__fsub_rn(__fmul_rn(a11, a22), __fmul_rn(a12, a21)), det);
    inv[1] = __fdiv_rn(__fsub_rn(__fmul_rn(a02, a21), __fmul_rn(a01, a22)), det);
    inv[2] = __fdiv_rn(__fsub_rn(__fmul_rn(a01, a12), __fmul_rn(a02, a11)), det);
    inv[3] = __fdiv_rn(__fsub_rn(__fmul_rn(a12, a20), __fmul_rn(a10, a22)), det);
    inv[4] = __fdiv_rn(__fsub_rn(__fmul_rn(a00, a22), __fmul_rn(a02, a20)), det);
    inv[5] = __fdiv_rn(__fsub_rn(__fmul_rn(a02, a10), __fmul_rn(a00, a12)), det);
    inv[6] = __fdiv_rn(__fsub_rn(__fmul_rn(a10, a21), __fmul_rn(a11, a20)), det);
    inv[7] = __fdiv_rn(__fsub_rn(__fmul_rn(a01, a20), __fmul_rn(a00, a21)), det);
    inv[8] = __fdiv_rn(__fsub_rn(__fmul_rn(a00, a11), __fmul_rn(a01, a10)), det);

    const float* P = pose + i * 16;
    #pragma unroll
    for (int r = 0; r < 3; r++) {
        float r0 = P[r * 4 + 0], r1 = P[r * 4 + 1], r2 = P[r * 4 + 2];
        #pragma unroll
        for (int c = 0; c < 3; c++) {
            cm[r * 3 + c] = __fadd_rn(
                __fadd_rn(__fmul_rn(r0, inv[0 * 3 + c]),
                          __fmul_rn(r1, inv[1 * 3 + c])),
                __fmul_rn(r2, inv[2 * 3 + c]));
        }
    }
    tr[0] = P[3];
    tr[1] = P[7];
    tr[2] = P[11];
}

__device__ __forceinline__ void red_v4(float* p, float4 a) {
    asm volatile("red.global.add.v4.f32 [%0], {%1, %2, %3, %4};" ::
                 "l"(p), "f"(a.x), "f"(a.y), "f"(a.z), "f"(a.w)
                 : "memory");
}

// ---------------------------------------------------------------------------
// Scatter: one warp = FOUR rays (8 lanes each, 8 channels per lane).
// Per ray: compute all 4 cell ids, then (fast path: all equal) issue all 8
// float4 loads back-to-back (MLP 8) and flush once with two
// red.global.add.v4.f32. Generic fallback handles per-n differing cells.
// [UNCHANGED — measured at its DRAM read roofline ~20 us]
// ---------------------------------------------------------------------------
__global__ __launch_bounds__(256) void fp_scatter_kernel(
    const float* __restrict__ x,
    const float* __restrict__ intr,
    const float* __restrict__ pose) {
    __shared__ float s_cm[Bv * Nv][9];
    __shared__ float s_tr[Bv * Nv][3];
    int t = threadIdx.x;
    if (t < Bv * Nv) compute_combine(intr, pose, t, s_cm[t], s_tr[t]);
    __syncthreads();

    const int P = Bv * Dv * Hv * Wv;  // 161280 rays
    int gwarp = (blockIdx.x * 256 + t) >> 5;
    int lane = t & 31;
    int r = gwarp * 4 + (lane >> 3);
    if (r >= P) return;
    int c8 = (lane & 7) * 8;  // channel group base

    int w = r % Wv;
    int tt = r / Wv;
    int h = tt % Hv;
    tt /= Hv;
    int d = tt % Dv;
    int b = tt / Dv;

    // Frustum point (linspace with forced endpoints, matching numpy/jnp)
    float du = __fdiv_rn((float)(Wv * 8 - 1), (float)(Wv - 1));  // 479/59
    float dv = __fdiv_rn((float)(Hv * 8 - 1), (float)(Hv - 1));  // 223/27
    float u = (w == Wv - 1) ? (float)(Wv * 8 - 1) : __fmul_rn((float)w, du);
    float v = (h == Hv - 1) ? (float)(Hv * 8 - 1) : __fmul_rn((float)h, dv);
    float dd = __fadd_rn(2.0f, (float)d);
    float ud = __fmul_rn(u, dd);
    float vd = __fmul_rn(v, dd);

    int cells[Nv];
    #pragma unroll
    for (int n = 0; n < Nv; n++) {
        const float* cm = s_cm[b * Nv + n];
        const float* tr = s_tr[b * Nv + n];
        float g0 = __fadd_rn(
            __fadd_rn(__fadd_rn(__fmul_rn(cm[0], ud), __fmul_rn(cm[1], vd)),
                      __fmul_rn(cm[2], dd)),
            tr[0]);
        float g1 = __fadd_rn(
            __fadd_rn(__fadd_rn(__fmul_rn(cm[3], ud), __fmul_rn(cm[4], vd)),
                      __fmul_rn(cm[5], dd)),
            tr[1]);
        float g2 = __fadd_rn(
            __fadd_rn(__fadd_rn(__fmul_rn(cm[6], ud), __fmul_rn(cm[7], vd)),
                      __fmul_rn(cm[8], dd)),
            tr[2]);
        int gx = (int)__fadd_rn(__fmul_rn(g0, 4.0f), 96.0f);
        int gy = (int)__fadd_rn(__fmul_rn(g1, 4.0f), 96.0f);
        int gz = (int)__fdiv_rn(__fadd_rn(g2, 10.0f), 20.0f);
        bool kept = (gx >= 0) & (gx < NXv) & (gy >= 0) & (gy < NYv) &
                    (gz >= 0) & (gz < NZv);
        cells[n] = kept ? ((b * NYv + gy) * NXv + gx) : -1;
    }

    size_t xoff = (size_t)(((b * Nv * Dv + d) * Hv + h) * Wv + w) * Cv + c8;
    const size_t nstride = (size_t)Dv * Hv * Wv * Cv;

    bool alleq = (cells[0] == cells[1]) & (cells[1] == cells[2]) &
                 (cells[2] == cells[3]);
    if (alleq) {
        int cell = cells[0];
        if (cell < 0) return;
        float4 v0[Nv], v1[Nv];
        #pragma unroll
        for (int n = 0; n < Nv; n++) {
            const float4* p = (const float4*)(x + xoff + n * nstride);
            v0[n] = __ldg(p);
            v1[n] = __ldg(p + 1);
        }
        float4 a0 = v0[0], a1 = v1[0];
        #pragma unroll
        for (int n = 1; n < Nv; n++) {
            a0.x += v0[n].x; a0.y += v0[n].y; a0.z += v0[n].z; a0.w += v0[n].w;
            a1.x += v1[n].x; a1.y += v1[n].y; a1.z += v1[n].z; a1.w += v1[n].w;
        }
        float* p = (float*)g_staging4 + (size_t)cell * Cv + c8;
        red_v4(p, a0);
        red_v4(p + 4, a1);
    } else {
        float4 a0 = make_float4(0, 0, 0, 0), a1 = make_float4(0, 0, 0, 0);
        int cur = -1;
        #pragma unroll
        for (int n = 0; n < Nv; n++) {
            if (cells[n] != cur) {
                if (cur >= 0) {
                    float* p = (float*)g_staging4 + (size_t)cur * Cv + c8;
                    red_v4(p, a0);
                    red_v4(p + 4, a1);
                }
                a0 = make_float4(0, 0, 0, 0);
                a1 = make_float4(0, 0, 0, 0);
                cur = cells[n];
            }
            if (cells[n] >= 0) {
                const float4* p = (const float4*)(x + xoff + n * nstride);
                float4 w0 = __ldg(p), w1 = __ldg(p + 1);
                a0.x += w0.x; a0.y += w0.y; a0.z += w0.z; a0.w += w0.w;
                a1.x += w1.x; a1.y += w1.y; a1.z += w1.z; a1.w += w1.w;
            }
        }
        if (cur >= 0) {
            float* p = (float*)g_staging4 + (size_t)cur * Cv + c8;
            red_v4(p, a0);
            red_v4(p + 4, a1);
        }
    }
}

// ---------------------------------------------------------------------------
// Transpose staging (B, NY, NX, C) -> out (B, C, NY, NX).
// One block = one (b, gy) row half: 96 gx x 64 c (25.6 KB smem -> 8 blocks/SM
// -> the whole 768-block grid is a single fully-resident wave).
// Phase 1: 6 independent LDG.128 per thread issued up front (MLP 6), then
//   conflict-free scalar STS (warp = 32 consecutive gx, c4u warp-uniform
//   because 96 = 3*32; bank = (16*c4u + 4j + gx) % 32 -> 32 distinct).
// Phase 2: conflict-free LDS.128 (stride 100 floats, 16B aligned), float4
//   STG in 384-byte contiguous runs per c-plane (3x longer than R4/R5).
// Tail: re-zero staging with 6 contiguous float4 STG per thread (R4 lesson:
//   never STG an address right after LDG-ing it).
// ---------------------------------------------------------------------------
#define GXW 96                     // gx width per block
#define TS 100                     // smem row stride in floats

__global__ __launch_bounds__(256) void fp_transpose_kernel(float* __restrict__ out) {
    __shared__ float tile[Cv * TS];  // 64 x 100 floats = 25.6 KB
    int t = threadIdx.x;
    int blk = blockIdx.x;
    int gxh = blk & 1;               // half-row selector
    int t1 = blk >> 1;
    int gy = t1 % NYv;
    int b = t1 / NYv;

    float4* src = g_staging4 +
        ((size_t)(b * NYv + gy) * NXv + gxh * GXW) * (Cv / 4);  // 1536 float4

    // Phase 1: load 6 float4 (all independent), scatter into smem c-major.
    float4 v[6];
    int gxA[6], c4A[6];
    #pragma unroll
    for (int k = 0; k < 6; k++) {
        int uu = t + k * 256;        // 0..1535
        int c4u = uu / GXW;          // 0..15 (warp-uniform: 96 = 3*32)
        int gx = uu - c4u * GXW;     // 0..95
        gxA[k] = gx;
        c4A[k] = c4u;
        v[k] = src[gx * (Cv / 4) + c4u];
    }
    #pragma unroll
    for (int k = 0; k < 6; k++) {
        float* row = tile + (c4A[k] * 4) * TS + gxA[k];
        row[0 * TS] = v[k].x;
        row[1 * TS] = v[k].y;
        row[2 * TS] = v[k].z;
        row[3 * TS] = v[k].w;
    }
    __syncthreads();

    // Phase 2: write out (b, c, gy, gx) in contiguous 384B runs per c.
    #pragma unroll
    for (int k = 0; k < 6; k++) {
        int uu = t + k * 256;        // 0..1535
        int c = uu / (GXW / 4);      // 0..63
        int gxi = uu - c * (GXW / 4);// 0..23 (float4 index)
        const float4* s4 = (const float4*)(tile + c * TS + gxi * 4);
        float4 o = *s4;
        float4* dst = (float4*)(out + (size_t)(b * Cv + c) * NYNX +
                                gy * NXv + gxh * GXW + gxi * 4);
        *dst = o;
    }

    // Tail: restore staging to zero (contiguous, fire-and-forget).
    const float4 z4 = make_float4(0.f, 0.f, 0.f, 0.f);
    #pragma unroll
    for (int k = 0; k < 6; k++) src[t + k * 256] = z4;
}

extern "C" void kernel_launch(void* const* d_in, const int* in_sizes, int n_in,
                              void* d_out, int out_size) {
    const float* x = (const float*)d_in[0];
    const float* intr = (const float*)d_in[1];
    const float* pose = (const float*)d_in[2];
    float* out = (float*)d_out;

    // 1) scatter (4 rays per warp, vector atomics into zeroed staging)
    const int P = Bv * Dv * Hv * Wv;      // 161280 rays
    int blocks = P / 4 / 8;               // 5040 blocks of 8 warps
    fp_scatter_kernel<<<blocks, 256>>>(x, intr, pose);

    // 2) transpose staging -> out (row-half per block, single wave);
    //    re-zeroes staging at its tail
    int tblocks = Bv * NYv * 2;           // 768
    fp_transpose_kernel<<<tblocks, 256>>>(out);
}

// round 10
// speedup vs baseline: 1.1319x; 1.1319x over previous
#include <cuda_runtime.h>
#include <cuda_bf16.h>
#include <stdint.h>

// Problem constants
#define Bv 2
#define Nv 4
#define Dv 48
#define Hv 28
#define Wv 60
#define Cv 64
#define NXv 192
#define NYv 192
#define NZv 1
#define NYNX (NYv * NXv)

// Channel-contiguous staging accumulator: [B*NY*NX][64] floats (18.9 MB).
// BSS-zeroed at module load; the transpose kernel restores it to zero at its
// tail every launch, so it is always zero when the next scatter begins.
__device__ float4 g_staging4[(size_t)Bv * NYv * NXv * (Cv / 4)];

// ---------------------------------------------------------------------------
// Per-block setup (in smem): invert intrinsics element-wise by det (matches
// LU back-substitution bit-for-bit on this matrix structure — validated
// rel_err 2.5e-7 across R1-R6), combine = R @ inv(K), stash translation.
// ---------------------------------------------------------------------------
__device__ __forceinline__ void compute_combine(
    const float* __restrict__ intr, const float* __restrict__ pose,
    int i, float* cm, float* tr) {
    const float* K = intr + i * 9;
    float a00 = K[0], a01 = K[1], a02 = K[2];
    float a10 = K[3], a11 = K[4], a12 = K[5];
    float a20 = K[6], a21 = K[7], a22 = K[8];

    float det = __fadd_rn(
        __fsub_rn(__fmul_rn(a00, __fsub_rn(__fmul_rn(a11, a22), __fmul_rn(a12, a21))),
                  __fmul_rn(a01, __fsub_rn(__fmul_rn(a10, a22), __fmul_rn(a12, a20)))),
        __fmul_rn(a02, __fsub_rn(__fmul_rn(a10, a21), __fmul_rn(a11, a20))));

    float inv[9];
    inv[0] = __fdiv_rn(__fsub_rn(__fmul_rn(a11, a22), __fmul_rn(a12, a21)), det);
    inv[1] = __fdiv_rn(__fsub_rn(__fmul_rn(a02, a21), __fmul_rn(a01, a22)), det);
    inv[2] = __fdiv_rn(__fsub_rn(__fmul_rn(a01, a12), __fmul_rn(a02, a11)), det);
    inv[3] = __fdiv_rn(__fsub_rn(__fmul_rn(a12, a20), __fmul_rn(a10, a22)), det);
    inv[4] = __fdiv_rn(__fsub_rn(__fmul_rn(a00, a22), __fmul_rn(a02, a20)), det);
    inv[5] = __fdiv_rn(__fsub_rn(__fmul_rn(a02, a10), __fmul_rn(a00, a12)), det);
    inv[6] = __fdiv_rn(__fsub_rn(__fmul_rn(a10, a21), __fmul_rn(a11, a20)), det);
    inv[7] = __fdiv_rn(__fsub_rn(__fmul_rn(a01, a20), __fmul_rn(a00, a21)), det);
    inv[8] = __fdiv_rn(__fsub_rn(__fmul_rn(a00, a11), __fmul_rn(a01, a10)), det);

    const float* P = pose + i * 16;
    #pragma unroll
    for (int r = 0; r < 3; r++) {
        float r0 = P[r * 4 + 0], r1 = P[r * 4 + 1], r2 = P[r * 4 + 2];
        #pragma unroll
        for (int c = 0; c < 3; c++) {
            cm[r * 3 + c] = __fadd_rn(
                __fadd_rn(__fmul_rn(r0, inv[0 * 3 + c]),
                          __fmul_rn(r1, inv[1 * 3 + c])),
                __fmul_rn(r2, inv[2 * 3 + c]));
        }
    }
    tr[0] = P[3];
    tr[1] = P[7];
    tr[2] = P[11];
}

__device__ __forceinline__ void red_v4(float* p, float4 a) {
    asm volatile("red.global.add.v4.f32 [%0], {%1, %2, %3, %4};" ::
                 "l"(p), "f"(a.x), "f"(a.y), "f"(a.z), "f"(a.w)
                 : "memory");
}

// Streaming (evict-first) float4 load: x is read exactly once — keep it from
// evicting the L2-resident staging buffer.
__device__ __forceinline__ float4 ldcs4(const float4* p) {
    float4 r;
    asm volatile("ld.global.cs.v4.f32 {%0, %1, %2, %3}, [%4];"
                 : "=f"(r.x), "=f"(r.y), "=f"(r.z), "=f"(r.w) : "l"(p));
    return r;
}

// Streaming float4 store: out is written once, never read.
__device__ __forceinline__ void stcs4(float4* p, float4 a) {
    asm volatile("st.global.cs.v4.f32 [%0], {%1, %2, %3, %4};" ::
                 "l"(p), "f"(a.x), "f"(a.y), "f"(a.z), "f"(a.w) : "memory");
}

// ---------------------------------------------------------------------------
// Scatter: one warp = FOUR rays (8 lanes each, 8 channels per lane).
// Per ray: compute all 4 cell ids, then (fast path: all equal) issue all 8
// float4 loads back-to-back (MLP 8) and flush once with two
// red.global.add.v4.f32. Generic fallback handles per-n differing cells.
// Only change vs R4: x loads use streaming hint (.cs).
// ---------------------------------------------------------------------------
__global__ __launch_bounds__(256) void fp_scatter_kernel(
    const float* __restrict__ x,
    const float* __restrict__ intr,
    const float* __restrict__ pose) {
    __shared__ float s_cm[Bv * Nv][9];
    __shared__ float s_tr[Bv * Nv][3];
    int t = threadIdx.x;
    if (t < Bv * Nv) compute_combine(intr, pose, t, s_cm[t], s_tr[t]);
    __syncthreads();

    const int P = Bv * Dv * Hv * Wv;  // 161280 rays
    int gwarp = (blockIdx.x * 256 + t) >> 5;
    int lane = t & 31;
    int r = gwarp * 4 + (lane >> 3);
    if (r >= P) return;
    int c8 = (lane & 7) * 8;  // channel group base

    int w = r % Wv;
    int tt = r / Wv;
    int h = tt % Hv;
    tt /= Hv;
    int d = tt % Dv;
    int b = tt / Dv;

    // Frustum point (linspace with forced endpoints, matching numpy/jnp)
    float du = __fdiv_rn((float)(Wv * 8 - 1), (float)(Wv - 1));  // 479/59
    float dv = __fdiv_rn((float)(Hv * 8 - 1), (float)(Hv - 1));  // 223/27
    float u = (w == Wv - 1) ? (float)(Wv * 8 - 1) : __fmul_rn((float)w, du);
    float v = (h == Hv - 1) ? (float)(Hv * 8 - 1) : __fmul_rn((float)h, dv);
    float dd = __fadd_rn(2.0f, (float)d);
    float ud = __fmul_rn(u, dd);
    float vd = __fmul_rn(v, dd);

    int cells[Nv];
    #pragma unroll
    for (int n = 0; n < Nv; n++) {
        const float* cm = s_cm[b * Nv + n];
        const float* tr = s_tr[b * Nv + n];
        float g0 = __fadd_rn(
            __fadd_rn(__fadd_rn(__fmul_rn(cm[0], ud), __fmul_rn(cm[1], vd)),
                      __fmul_rn(cm[2], dd)),
            tr[0]);
        float g1 = __fadd_rn(
            __fadd_rn(__fadd_rn(__fmul_rn(cm[3], ud), __fmul_rn(cm[4], vd)),
                      __fmul_rn(cm[5], dd)),
            tr[1]);
        float g2 = __fadd_rn(
            __fadd_rn(__fadd_rn(__fmul_rn(cm[6], ud), __fmul_rn(cm[7], vd)),
                      __fmul_rn(cm[8], dd)),
            tr[2]);
        int gx = (int)__fadd_rn(__fmul_rn(g0, 4.0f), 96.0f);
        int gy = (int)__fadd_rn(__fmul_rn(g1, 4.0f), 96.0f);
        int gz = (int)__fdiv_rn(__fadd_rn(g2, 10.0f), 20.0f);
        bool kept = (gx >= 0) & (gx < NXv) & (gy >= 0) & (gy < NYv) &
                    (gz >= 0) & (gz < NZv);
        cells[n] = kept ? ((b * NYv + gy) * NXv + gx) : -1;
    }

    size_t xoff = (size_t)(((b * Nv * Dv + d) * Hv + h) * Wv + w) * Cv + c8;
    const size_t nstride = (size_t)Dv * Hv * Wv * Cv;

    bool alleq = (cells[0] == cells[1]) & (cells[1] == cells[2]) &
                 (cells[2] == cells[3]);
    if (alleq) {
        int cell = cells[0];
        if (cell < 0) return;
        float4 v0[Nv], v1[Nv];
        #pragma unroll
        for (int n = 0; n < Nv; n++) {
            const float4* p = (const float4*)(x + xoff + n * nstride);
            v0[n] = ldcs4(p);
            v1[n] = ldcs4(p + 1);
        }
        float4 a0 = v0[0], a1 = v1[0];
        #pragma unroll
        for (int n = 1; n < Nv; n++) {
            a0.x += v0[n].x; a0.y += v0[n].y; a0.z += v0[n].z; a0.w += v0[n].w;
            a1.x += v1[n].x; a1.y += v1[n].y; a1.z += v1[n].z; a1.w += v1[n].w;
        }
        float* p = (float*)g_staging4 + (size_t)cell * Cv + c8;
        red_v4(p, a0);
        red_v4(p + 4, a1);
    } else {
        float4 a0 = make_float4(0, 0, 0, 0), a1 = make_float4(0, 0, 0, 0);
        int cur = -1;
        #pragma unroll
        for (int n = 0; n < Nv; n++) {
            if (cells[n] != cur) {
                if (cur >= 0) {
                    float* p = (float*)g_staging4 + (size_t)cur * Cv + c8;
                    red_v4(p, a0);
                    red_v4(p + 4, a1);
                }
                a0 = make_float4(0, 0, 0, 0);
                a1 = make_float4(0, 0, 0, 0);
                cur = cells[n];
            }
            if (cells[n] >= 0) {
                const float4* p = (const float4*)(x + xoff + n * nstride);
                float4 w0 = ldcs4(p), w1 = ldcs4(p + 1);
                a0.x += w0.x; a0.y += w0.y; a0.z += w0.z; a0.w += w0.w;
                a1.x += w1.x; a1.y += w1.y; a1.z += w1.z; a1.w += w1.w;
            }
        }
        if (cur >= 0) {
            float* p = (float*)g_staging4 + (size_t)cur * Cv + c8;
            red_v4(p, a0);
            red_v4(p + 4, a1);
        }
    }
}

// ---------------------------------------------------------------------------
// Transpose staging (B, NY, NX, C) -> out (B, C, NY, NX), float4 both ways.
// EXACT R4 structure (empirical best: 11.2 us; two redesigns regressed).
// Staging re-zero deferred to the kernel tail (R4 lesson: same-address
// STG-after-LDG parks behind the load in L1tex and stalls the LSU).
// Only change vs R4: out stores use streaming hint (.cs).
// ---------------------------------------------------------------------------
__global__ __launch_bounds__(256) void fp_transpose_kernel(float* __restrict__ out) {
    __shared__ float tile[32 * 65];
    int blk = blockIdx.x;
    int gxt = blk % (NXv / 32);
    int t1 = blk / (NXv / 32);
    int gy = t1 % NYv;
    int b = t1 / NYv;
    int gx0 = gxt * 32;
    int t = threadIdx.x;

    float4* src = g_staging4 + ((size_t)(b * NYv + gy) * NXv + gx0) * (Cv / 4);

    #pragma unroll
    for (int it = 0; it < 2; it++) {
        int uu = t + it * 256;       // 0..511 float4 units
        int gx = uu >> 4;
        int c4 = (uu & 15) * 4;
        float4 vv = src[uu];
        tile[gx * 65 + c4 + 0] = vv.x;
        tile[gx * 65 + c4 + 1] = vv.y;
        tile[gx * 65 + c4 + 2] = vv.z;
        tile[gx * 65 + c4 + 3] = vv.w;
    }
    __syncthreads();

    #pragma unroll
    for (int it = 0; it < 2; it++) {
        int uu = t + it * 256;       // 0..511 output float4 units
        int gx4 = uu & 7;            // 4-wide gx group
        int c = uu >> 3;             // 0..63
        float4 o;
        o.x = tile[(gx4 * 4 + 0) * 65 + c];
        o.y = tile[(gx4 * 4 + 1) * 65 + c];
        o.z = tile[(gx4 * 4 + 2) * 65 + c];
        o.w = tile[(gx4 * 4 + 3) * 65 + c];
        float4* dst = (float4*)(out + (size_t)(b * Cv + c) * NYNX +
                                gy * NXv + gx0 + gx4 * 4);
        stcs4(dst, o);
    }

    // Tail: restore staging to zero for the next graph replay (fire-and-
    // forget stores; the matching loads completed long ago). Default cache
    // policy on purpose — staging should STAY L2-resident for the next
    // scatter's atomics.
    const float4 z4 = make_float4(0.f, 0.f, 0.f, 0.f);
    src[t] = z4;
    src[t + 256] = z4;
}

extern "C" void kernel_launch(void* const* d_in, const int* in_sizes, int n_in,
                              void* d_out, int out_size) {
    const float* x = (const float*)d_in[0];
    const float* intr = (const float*)d_in[1];
    const float* pose = (const float*)d_in[2];
    float* out = (float*)d_out;

    // 1) scatter (4 rays per warp, vector atomics into zeroed staging)
    const int P = Bv * Dv * Hv * Wv;      // 161280 rays
    int blocks = P / 4 / 8;               // 5040 blocks of 8 warps
    fp_scatter_kernel<<<blocks, 256>>>(x, intr, pose);

    // 2) transpose staging -> out; re-zeroes staging at its tail
    int tblocks = Bv * NYv * (NXv / 32);  // 2304
    fp_transpose_kernel<<<tblocks, 256>>>(out);
}